// round 1
// baseline (speedup 1.0000x reference)
#include <cuda_runtime.h>

#define NN   80000
#define EE   1280000
#define ET   (EE + NN)
#define HH   64
#define FIND 128
#define OUTD 10

// ---------------- scratch (no allocations allowed) ----------------
__device__ float g_xl[(size_t)NN * HH];
__device__ float g_xr[(size_t)NN * HH];
__device__ float g_h1[(size_t)NN * HH];
__device__ float g_h2[(size_t)NN * HH];
__device__ int   g_deg[NN];
__device__ int   g_off[NN + 1];
__device__ int   g_cur[NN];
__device__ int   g_src[ET];

// ---------------- CSR build ----------------
__global__ void deg_init_kernel() {
    int i = blockIdx.x * blockDim.x + threadIdx.x;
    if (i < NN) g_deg[i] = 1;   // self loop
}

__global__ void count_kernel(const int* __restrict__ ei) {
    int i = blockIdx.x * blockDim.x + threadIdx.x;
    if (i < EE) atomicAdd(&g_deg[ei[EE + i]], 1);
}

// single-block exclusive scan over g_deg -> g_off
__global__ void scan_kernel() {
    __shared__ int wsum[32];
    int lane = threadIdx.x & 31, wid = threadIdx.x >> 5;
    int carry = 0;
    for (int base = 0; base < NN; base += 1024) {
        int i = base + threadIdx.x;
        int v = (i < NN) ? g_deg[i] : 0;
        int x = v;
        #pragma unroll
        for (int d = 1; d < 32; d <<= 1) {
            int y = __shfl_up_sync(0xffffffffu, x, d);
            if (lane >= d) x += y;
        }
        if (lane == 31) wsum[wid] = x;
        __syncthreads();
        if (wid == 0) {
            int s = wsum[lane];
            #pragma unroll
            for (int d = 1; d < 32; d <<= 1) {
                int y = __shfl_up_sync(0xffffffffu, s, d);
                if (lane >= d) s += y;
            }
            wsum[lane] = s;
        }
        __syncthreads();
        int pre = wid ? wsum[wid - 1] : 0;
        if (i < NN) g_off[i] = carry + pre + x - v;
        int tot = wsum[31];
        __syncthreads();
        carry += tot;
    }
    if (threadIdx.x == 0) g_off[NN] = carry;
}

__global__ void cursor_kernel() {
    int i = blockIdx.x * blockDim.x + threadIdx.x;
    if (i < NN) g_cur[i] = g_off[i];
}

__global__ void scatter_kernel(const int* __restrict__ ei) {
    int i = blockIdx.x * blockDim.x + threadIdx.x;
    if (i < ET) {
        int s, d;
        if (i < EE) { s = ei[i]; d = ei[EE + i]; }
        else        { s = i - EE; d = s; }
        int p = atomicAdd(&g_cur[d], 1);
        g_src[p] = s;
    }
}

// ---------------- fused xl/xr projection: [N,fin] @ Wl^T, Wr^T -> g_xl, g_xr ----------------
// tile: 128 nodes x 64 H, k-chunks of 32, thread = 8 nodes x 4 H for both outputs
__global__ __launch_bounds__(256) void dual_linear_kernel(
    const float* __restrict__ A, int fin,
    const float* __restrict__ Wl, const float* __restrict__ bl,
    const float* __restrict__ Wr, const float* __restrict__ br)
{
    __shared__ float As[128 * 40];     // [n][k] padded
    __shared__ float Wls[32 * 64];     // [k][h]
    __shared__ float Wrs[32 * 64];

    int t  = threadIdx.x;
    int tx = t & 15;        // h group (4 h each)
    int ty = t >> 4;        // n group (8 n each)
    int n0 = blockIdx.x * 128;

    float accl[8][4], accr[8][4];
    #pragma unroll
    for (int i = 0; i < 8; i++)
        #pragma unroll
        for (int j = 0; j < 4; j++) { accl[i][j] = 0.f; accr[i][j] = 0.f; }

    int arow = t >> 3;      // 0..31 (per iteration, +32 each)
    int ak4  = t & 7;       // float4 index along k
    int wh   = t & 63;
    int wkq  = (t >> 6) * 8;

    for (int kc = 0; kc < fin; kc += 32) {
        // load A tile (128 x 32) as [n][k]
        #pragma unroll
        for (int r = 0; r < 4; r++) {
            int row = arow + r * 32;
            float4 v = *(const float4*)(A + (size_t)(n0 + row) * fin + kc + ak4 * 4);
            *(float4*)(As + row * 40 + ak4 * 4) = v;
        }
        // load W tiles transposed as [k][h]
        #pragma unroll
        for (int j = 0; j < 2; j++) {
            int kb = wkq + j * 4;
            float4 v = *(const float4*)(Wl + (size_t)wh * fin + kc + kb);
            Wls[(kb + 0) * 64 + wh] = v.x;
            Wls[(kb + 1) * 64 + wh] = v.y;
            Wls[(kb + 2) * 64 + wh] = v.z;
            Wls[(kb + 3) * 64 + wh] = v.w;
            float4 u = *(const float4*)(Wr + (size_t)wh * fin + kc + kb);
            Wrs[(kb + 0) * 64 + wh] = u.x;
            Wrs[(kb + 1) * 64 + wh] = u.y;
            Wrs[(kb + 2) * 64 + wh] = u.z;
            Wrs[(kb + 3) * 64 + wh] = u.w;
        }
        __syncthreads();

        #pragma unroll
        for (int k = 0; k < 32; k++) {
            float a_[8];
            #pragma unroll
            for (int i = 0; i < 8; i++) a_[i] = As[(ty * 8 + i) * 40 + k];
            float4 wl = *(const float4*)(Wls + k * 64 + tx * 4);
            float4 wr = *(const float4*)(Wrs + k * 64 + tx * 4);
            #pragma unroll
            for (int i = 0; i < 8; i++) {
                accl[i][0] += a_[i] * wl.x; accl[i][1] += a_[i] * wl.y;
                accl[i][2] += a_[i] * wl.z; accl[i][3] += a_[i] * wl.w;
                accr[i][0] += a_[i] * wr.x; accr[i][1] += a_[i] * wr.y;
                accr[i][2] += a_[i] * wr.z; accr[i][3] += a_[i] * wr.w;
            }
        }
        __syncthreads();
    }

    float4 blv = *(const float4*)(bl + tx * 4);
    float4 brv = *(const float4*)(br + tx * 4);
    #pragma unroll
    for (int i = 0; i < 8; i++) {
        int row = n0 + ty * 8 + i;
        float4 o;
        o.x = accl[i][0] + blv.x; o.y = accl[i][1] + blv.y;
        o.z = accl[i][2] + blv.z; o.w = accl[i][3] + blv.w;
        *(float4*)(g_xl + (size_t)row * HH + tx * 4) = o;
        float4 p;
        p.x = accr[i][0] + brv.x; p.y = accr[i][1] + brv.y;
        p.z = accr[i][2] + brv.z; p.w = accr[i][3] + brv.w;
        *(float4*)(g_xr + (size_t)row * HH + tx * 4) = p;
    }
}

// ---------------- per-destination online-softmax aggregation (warp per node) ----------------
__global__ __launch_bounds__(256) void gat_edge_kernel(
    const float* __restrict__ att, const float* __restrict__ b,
    float* __restrict__ hout)
{
    int warp = blockIdx.x * (blockDim.x >> 5) + (threadIdx.x >> 5);
    if (warp >= NN) return;
    int lane = threadIdx.x & 31;
    int node = warp;

    float att0 = __ldg(att + lane);
    float att1 = __ldg(att + 32 + lane);
    float xr0  = g_xr[(size_t)node * HH + lane];
    float xr1  = g_xr[(size_t)node * HH + 32 + lane];

    int s = g_off[node], e = g_off[node + 1];

    float m = -1e30f, d = 0.f, acc0 = 0.f, acc1 = 0.f;
    for (int i = s; i < e; i++) {
        int src = g_src[i];
        float a0 = __ldg(g_xl + (size_t)src * HH + lane);
        float a1 = __ldg(g_xl + (size_t)src * HH + 32 + lane);
        float t0 = a0 + xr0; t0 = t0 > 0.f ? t0 : 0.2f * t0;
        float t1 = a1 + xr1; t1 = t1 > 0.f ? t1 : 0.2f * t1;
        float p = t0 * att0 + t1 * att1;
        #pragma unroll
        for (int o = 16; o; o >>= 1) p += __shfl_xor_sync(0xffffffffu, p, o);
        if (p > m) {                       // warp-uniform branch
            float sc = __expf(m - p);
            d *= sc; acc0 *= sc; acc1 *= sc; m = p;
        }
        float w = __expf(p - m);
        d += w; acc0 += w * a0; acc1 += w * a1;
    }
    float inv = __fdividef(1.f, d);
    float o0 = acc0 * inv + __ldg(b + lane);
    float o1 = acc1 * inv + __ldg(b + 32 + lane);
    hout[(size_t)node * HH + lane]      = o0 > 0.f ? o0 : 0.f;
    hout[(size_t)node * HH + 32 + lane] = o1 > 0.f ? o1 : 0.f;
}

// ---------------- readout: [N,64] @ Wro^T + bro -> [N,10] ----------------
__global__ __launch_bounds__(256) void readout_kernel(
    const float* __restrict__ h, const float* __restrict__ Wro,
    const float* __restrict__ bro, float* __restrict__ out)
{
    __shared__ float Ws[OUTD * HH];
    for (int i = threadIdx.x; i < OUTD * HH; i += blockDim.x) Ws[i] = Wro[i];
    __syncthreads();

    int warp = blockIdx.x * (blockDim.x >> 5) + (threadIdx.x >> 5);
    if (warp >= NN) return;
    int lane = threadIdx.x & 31;

    float h0 = h[(size_t)warp * HH + lane];
    float h1 = h[(size_t)warp * HH + 32 + lane];
    #pragma unroll
    for (int o = 0; o < OUTD; o++) {
        float p = h0 * Ws[o * HH + lane] + h1 * Ws[o * HH + 32 + lane];
        #pragma unroll
        for (int w = 16; w; w >>= 1) p += __shfl_xor_sync(0xffffffffu, p, w);
        if (lane == 0) out[(size_t)warp * OUTD + o] = p + __ldg(bro + o);
    }
}

// ---------------- launch ----------------
extern "C" void kernel_launch(void* const* d_in, const int* in_sizes, int n_in,
                              void* d_out, int out_size)
{
    const float* x  = (const float*)d_in[0];
    const int*   ei = (const int*)d_in[1];
    // d_in[2] = batch (unused)
    const float* Wl0 = (const float*)d_in[3];
    const float* bl0 = (const float*)d_in[4];
    const float* Wr0 = (const float*)d_in[5];
    const float* br0 = (const float*)d_in[6];
    const float* at0 = (const float*)d_in[7];
    const float* b0  = (const float*)d_in[8];
    const float* Wl1 = (const float*)d_in[9];
    const float* bl1 = (const float*)d_in[10];
    const float* Wr1 = (const float*)d_in[11];
    const float* br1 = (const float*)d_in[12];
    const float* at1 = (const float*)d_in[13];
    const float* b1  = (const float*)d_in[14];
    const float* Wl2 = (const float*)d_in[15];
    const float* bl2 = (const float*)d_in[16];
    const float* Wr2 = (const float*)d_in[17];
    const float* br2 = (const float*)d_in[18];
    const float* at2 = (const float*)d_in[19];
    const float* b2  = (const float*)d_in[20];
    const float* Wro = (const float*)d_in[21];
    const float* bro = (const float*)d_in[22];
    float* out = (float*)d_out;

    float *h1p, *h2p;
    cudaGetSymbolAddress((void**)&h1p, g_h1);
    cudaGetSymbolAddress((void**)&h2p, g_h2);

    // CSR build (per launch; deterministic up to fp-neutral atomic ordering)
    deg_init_kernel<<<(NN + 255) / 256, 256>>>();
    count_kernel<<<(EE + 255) / 256, 256>>>(ei);
    scan_kernel<<<1, 1024>>>();
    cursor_kernel<<<(NN + 255) / 256, 256>>>();
    scatter_kernel<<<(ET + 255) / 256, 256>>>(ei);

    const int GB = NN / 128;         // 625 GEMM blocks
    const int WB = NN / 8;           // 10000 warp-per-node blocks

    // layer 0
    dual_linear_kernel<<<GB, 256>>>(x, FIND, Wl0, bl0, Wr0, br0);
    gat_edge_kernel<<<WB, 256>>>(at0, b0, h1p);
    // layer 1
    dual_linear_kernel<<<GB, 256>>>(h1p, HH, Wl1, bl1, Wr1, br1);
    gat_edge_kernel<<<WB, 256>>>(at1, b1, h2p);
    // layer 2
    dual_linear_kernel<<<GB, 256>>>(h2p, HH, Wl2, bl2, Wr2, br2);
    gat_edge_kernel<<<WB, 256>>>(at2, b2, h1p);
    // readout
    readout_kernel<<<WB, 256>>>(h1p, Wro, bro, out);
}

// round 3
// speedup vs baseline: 1.0776x; 1.0776x over previous
#include <cuda_runtime.h>

#define NN   80000
#define EE   1280000
#define ET   (EE + NN)
#define HH   64
#define FIND 128
#define OUTD 10

// ---------------- scratch (no allocations allowed) ----------------
__device__ float g_xl[(size_t)NN * HH];
__device__ float g_xr[(size_t)NN * HH];
__device__ float g_h1[(size_t)NN * HH];
__device__ float g_h2[(size_t)NN * HH];
__device__ int   g_deg[NN];
__device__ int   g_off[NN + 1];
__device__ int   g_cur[NN];
__device__ int   g_src[ET];
__device__ int   g_bsum[128];
__device__ int   g_bpre[128];

// ---------------- CSR build ----------------
__global__ void deg_init_kernel() {
    int i = blockIdx.x * blockDim.x + threadIdx.x;
    if (i < NN) g_deg[i] = 1;   // self loop
}

__global__ void count_kernel(const int* __restrict__ ei) {
    int i = blockIdx.x * blockDim.x + threadIdx.x;
    if (i < EE) atomicAdd(&g_deg[ei[EE + i]], 1);
}

// hierarchical scan: per-block exclusive scan of 1024 elems + block sums
__global__ __launch_bounds__(1024) void block_scan_kernel() {
    __shared__ int wsum[32];
    int lane = threadIdx.x & 31, wid = threadIdx.x >> 5;
    int i = blockIdx.x * 1024 + threadIdx.x;
    int v = (i < NN) ? g_deg[i] : 0;
    int x = v;
    #pragma unroll
    for (int d = 1; d < 32; d <<= 1) {
        int y = __shfl_up_sync(0xffffffffu, x, d);
        if (lane >= d) x += y;
    }
    if (lane == 31) wsum[wid] = x;
    __syncthreads();
    if (wid == 0) {
        int s = wsum[lane];
        #pragma unroll
        for (int d = 1; d < 32; d <<= 1) {
            int y = __shfl_up_sync(0xffffffffu, s, d);
            if (lane >= d) s += y;
        }
        wsum[lane] = s;
    }
    __syncthreads();
    int pre = wid ? wsum[wid - 1] : 0;
    if (i < NN) g_off[i] = pre + x - v;      // block-local exclusive
    if (threadIdx.x == 1023) g_bsum[blockIdx.x] = pre + x;
}

// scan the (<=128) block sums in one warp-ish block
__global__ void bsum_scan_kernel(int nb) {
    int lane = threadIdx.x;                  // 128 threads
    int v = (lane < nb) ? g_bsum[lane] : 0;
    int x = v;
    #pragma unroll
    for (int d = 1; d < 32; d <<= 1) {
        int y = __shfl_up_sync(0xffffffffu, x, d);
        if ((lane & 31) >= d) x += y;
    }
    __shared__ int ws[4];
    if ((lane & 31) == 31) ws[lane >> 5] = x;
    __syncthreads();
    int add = 0;
    for (int w = 0; w < (lane >> 5); w++) add += ws[w];
    if (lane < nb) g_bpre[lane] = add + x - v;   // exclusive prefix
}

// add block prefixes, init cursors, set sentinel
__global__ void add_offsets_kernel() {
    int i = blockIdx.x * blockDim.x + threadIdx.x;
    if (i < NN) {
        int o = g_off[i] + g_bpre[i >> 10];
        g_off[i] = o;
        g_cur[i] = o;
    }
    if (i == 0) g_off[NN] = ET;              // total degree is a known constant
}

__global__ void scatter_kernel(const int* __restrict__ ei) {
    int i = blockIdx.x * blockDim.x + threadIdx.x;
    if (i < ET) {
        int s, d;
        if (i < EE) { s = ei[i]; d = ei[EE + i]; }
        else        { s = i - EE; d = s; }
        int p = atomicAdd(&g_cur[d], 1);
        g_src[p] = s;
    }
}

// ---------------- fused xl/xr projection: [N,fin] @ Wl^T, Wr^T -> g_xl, g_xr ----------------
__global__ __launch_bounds__(256) void dual_linear_kernel(
    const float* __restrict__ A, int fin,
    const float* __restrict__ Wl, const float* __restrict__ bl,
    const float* __restrict__ Wr, const float* __restrict__ br)
{
    __shared__ float As[128 * 40];     // [n][k] padded
    __shared__ float Wls[32 * 64];     // [k][h]
    __shared__ float Wrs[32 * 64];

    int t  = threadIdx.x;
    int tx = t & 15;        // h group (4 h each)
    int ty = t >> 4;        // n group (8 n each)
    int n0 = blockIdx.x * 128;

    float accl[8][4], accr[8][4];
    #pragma unroll
    for (int i = 0; i < 8; i++)
        #pragma unroll
        for (int j = 0; j < 4; j++) { accl[i][j] = 0.f; accr[i][j] = 0.f; }

    int arow = t >> 3;      // 0..31 (per iteration, +32 each)
    int ak4  = t & 7;       // float4 index along k
    int wh   = t & 63;
    int wkq  = (t >> 6) * 8;

    for (int kc = 0; kc < fin; kc += 32) {
        #pragma unroll
        for (int r = 0; r < 4; r++) {
            int row = arow + r * 32;
            float4 v = *(const float4*)(A + (size_t)(n0 + row) * fin + kc + ak4 * 4);
            *(float4*)(As + row * 40 + ak4 * 4) = v;
        }
        #pragma unroll
        for (int j = 0; j < 2; j++) {
            int kb = wkq + j * 4;
            float4 v = *(const float4*)(Wl + (size_t)wh * fin + kc + kb);
            Wls[(kb + 0) * 64 + wh] = v.x;
            Wls[(kb + 1) * 64 + wh] = v.y;
            Wls[(kb + 2) * 64 + wh] = v.z;
            Wls[(kb + 3) * 64 + wh] = v.w;
            float4 u = *(const float4*)(Wr + (size_t)wh * fin + kc + kb);
            Wrs[(kb + 0) * 64 + wh] = u.x;
            Wrs[(kb + 1) * 64 + wh] = u.y;
            Wrs[(kb + 2) * 64 + wh] = u.z;
            Wrs[(kb + 3) * 64 + wh] = u.w;
        }
        __syncthreads();

        #pragma unroll
        for (int k = 0; k < 32; k++) {
            float a_[8];
            #pragma unroll
            for (int i = 0; i < 8; i++) a_[i] = As[(ty * 8 + i) * 40 + k];
            float4 wl = *(const float4*)(Wls + k * 64 + tx * 4);
            float4 wr = *(const float4*)(Wrs + k * 64 + tx * 4);
            #pragma unroll
            for (int i = 0; i < 8; i++) {
                accl[i][0] += a_[i] * wl.x; accl[i][1] += a_[i] * wl.y;
                accl[i][2] += a_[i] * wl.z; accl[i][3] += a_[i] * wl.w;
                accr[i][0] += a_[i] * wr.x; accr[i][1] += a_[i] * wr.y;
                accr[i][2] += a_[i] * wr.z; accr[i][3] += a_[i] * wr.w;
            }
        }
        __syncthreads();
    }

    float4 blv = *(const float4*)(bl + tx * 4);
    float4 brv = *(const float4*)(br + tx * 4);
    #pragma unroll
    for (int i = 0; i < 8; i++) {
        int row = n0 + ty * 8 + i;
        float4 o;
        o.x = accl[i][0] + blv.x; o.y = accl[i][1] + blv.y;
        o.z = accl[i][2] + blv.z; o.w = accl[i][3] + blv.w;
        *(float4*)(g_xl + (size_t)row * HH + tx * 4) = o;
        float4 p;
        p.x = accr[i][0] + brv.x; p.y = accr[i][1] + brv.y;
        p.z = accr[i][2] + brv.z; p.w = accr[i][3] + brv.w;
        *(float4*)(g_xr + (size_t)row * HH + tx * 4) = p;
    }
}

// ---------------- per-destination online-softmax, 4 edges per warp-iteration ----------------
__global__ __launch_bounds__(256) void gat_edge_kernel(
    const float* __restrict__ att, const float* __restrict__ b,
    float* __restrict__ hout)
{
    int warp = blockIdx.x * (blockDim.x >> 5) + (threadIdx.x >> 5);
    if (warp >= NN) return;
    int lane = threadIdx.x & 31;
    int node = warp;

    float att0 = __ldg(att + lane);
    float att1 = __ldg(att + 32 + lane);
    float xr0  = g_xr[(size_t)node * HH + lane];
    float xr1  = g_xr[(size_t)node * HH + 32 + lane];

    int s = g_off[node], e = g_off[node + 1];

    float m = -3.0e38f, d = 0.f, acc0 = 0.f, acc1 = 0.f;
    for (int i = s; i < e; i += 4) {
        float a0[4], a1[4], p[4];
        #pragma unroll
        for (int j = 0; j < 4; j++) {
            bool valid = (i + j) < e;
            int src = valid ? g_src[i + j] : node;
            a0[j] = __ldg(g_xl + (size_t)src * HH + lane);
            a1[j] = __ldg(g_xl + (size_t)src * HH + 32 + lane);
            float t0 = a0[j] + xr0; t0 = t0 > 0.f ? t0 : 0.2f * t0;
            float t1 = a1[j] + xr1; t1 = t1 > 0.f ? t1 : 0.2f * t1;
            p[j] = valid ? (t0 * att0 + t1 * att1) : -3.0e38f;
        }
        // 4 independent butterfly chains — latency overlapped
        #pragma unroll
        for (int o = 16; o; o >>= 1) {
            #pragma unroll
            for (int j = 0; j < 4; j++)
                p[j] += __shfl_xor_sync(0xffffffffu, p[j], o);
        }
        float m4 = fmaxf(fmaxf(p[0], p[1]), fmaxf(p[2], p[3]));
        if (m4 > m) {                       // warp-uniform; once per 4 edges
            float sc = __expf(m - m4);
            d *= sc; acc0 *= sc; acc1 *= sc; m = m4;
        }
        #pragma unroll
        for (int j = 0; j < 4; j++) {
            float w = __expf(p[j] - m);     // invalid -> exp(-inf) = 0
            d += w; acc0 += w * a0[j]; acc1 += w * a1[j];
        }
    }
    float inv = __fdividef(1.f, d);
    float o0 = acc0 * inv + __ldg(b + lane);
    float o1 = acc1 * inv + __ldg(b + 32 + lane);
    hout[(size_t)node * HH + lane]      = o0 > 0.f ? o0 : 0.f;
    hout[(size_t)node * HH + 32 + lane] = o1 > 0.f ? o1 : 0.f;
}

// ---------------- readout: [N,64] @ Wro^T + bro -> [N,10] ----------------
__global__ __launch_bounds__(256) void readout_kernel(
    const float* __restrict__ h, const float* __restrict__ Wro,
    const float* __restrict__ bro, float* __restrict__ out)
{
    __shared__ float Ws[OUTD * HH];
    for (int i = threadIdx.x; i < OUTD * HH; i += blockDim.x) Ws[i] = Wro[i];
    __syncthreads();

    int warp = blockIdx.x * (blockDim.x >> 5) + (threadIdx.x >> 5);
    if (warp >= NN) return;
    int lane = threadIdx.x & 31;

    float h0 = h[(size_t)warp * HH + lane];
    float h1 = h[(size_t)warp * HH + 32 + lane];
    #pragma unroll
    for (int o = 0; o < OUTD; o++) {
        float p = h0 * Ws[o * HH + lane] + h1 * Ws[o * HH + 32 + lane];
        #pragma unroll
        for (int w = 16; w; w >>= 1) p += __shfl_xor_sync(0xffffffffu, p, w);
        if (lane == 0) out[(size_t)warp * OUTD + o] = p + __ldg(bro + o);
    }
}

// ---------------- launch ----------------
extern "C" void kernel_launch(void* const* d_in, const int* in_sizes, int n_in,
                              void* d_out, int out_size)
{
    const float* x  = (const float*)d_in[0];
    const int*   ei = (const int*)d_in[1];
    const float* Wl0 = (const float*)d_in[3];
    const float* bl0 = (const float*)d_in[4];
    const float* Wr0 = (const float*)d_in[5];
    const float* br0 = (const float*)d_in[6];
    const float* at0 = (const float*)d_in[7];
    const float* b0  = (const float*)d_in[8];
    const float* Wl1 = (const float*)d_in[9];
    const float* bl1 = (const float*)d_in[10];
    const float* Wr1 = (const float*)d_in[11];
    const float* br1 = (const float*)d_in[12];
    const float* at1 = (const float*)d_in[13];
    const float* b1  = (const float*)d_in[14];
    const float* Wl2 = (const float*)d_in[15];
    const float* bl2 = (const float*)d_in[16];
    const float* Wr2 = (const float*)d_in[17];
    const float* br2 = (const float*)d_in[18];
    const float* at2 = (const float*)d_in[19];
    const float* b2  = (const float*)d_in[20];
    const float* Wro = (const float*)d_in[21];
    const float* bro = (const float*)d_in[22];
    float* out = (float*)d_out;

    float *h1p, *h2p;
    cudaGetSymbolAddress((void**)&h1p, g_h1);
    cudaGetSymbolAddress((void**)&h2p, g_h2);

    const int NB = (NN + 1023) / 1024;   // 79 scan blocks

    // CSR build
    deg_init_kernel<<<(NN + 255) / 256, 256>>>();
    count_kernel<<<(EE + 255) / 256, 256>>>(ei);
    block_scan_kernel<<<NB, 1024>>>();
    bsum_scan_kernel<<<1, 128>>>(NB);
    add_offsets_kernel<<<(NN + 255) / 256, 256>>>();
    scatter_kernel<<<(ET + 255) / 256, 256>>>(ei);

    const int GB = NN / 128;         // 625 GEMM blocks
    const int WB = NN / 8;           // 10000 warp-per-node blocks

    dual_linear_kernel<<<GB, 256>>>(x, FIND, Wl0, bl0, Wr0, br0);
    gat_edge_kernel<<<WB, 256>>>(at0, b0, h1p);
    dual_linear_kernel<<<GB, 256>>>(h1p, HH, Wl1, bl1, Wr1, br1);
    gat_edge_kernel<<<WB, 256>>>(at1, b1, h2p);
    dual_linear_kernel<<<GB, 256>>>(h2p, HH, Wl2, bl2, Wr2, br2);
    gat_edge_kernel<<<WB, 256>>>(at2, b2, h1p);
    readout_kernel<<<WB, 256>>>(h1p, Wro, bro, out);
}

// round 5
// speedup vs baseline: 1.2598x; 1.1691x over previous
#include <cuda_runtime.h>

#define NN   80000
#define EE   1280000
#define ET   (EE + NN)
#define HH   64
#define FIND 128
#define OUTD 10

// ---------------- scratch ----------------
__device__ float g_xl[(size_t)NN * HH];
__device__ float g_xr[(size_t)NN * HH];
__device__ float g_h1[(size_t)NN * HH];
__device__ float g_h2[(size_t)NN * HH];
__device__ int   g_deg[NN];
__device__ int   g_off[NN + 1];
__device__ int   g_cur[NN];
__device__ int   g_src[ET];
__device__ int   g_bsum[128];

// ---------------- CSR build ----------------
__global__ void deg_init_kernel() {
    int i = blockIdx.x * blockDim.x + threadIdx.x;
    if (i < NN) g_deg[i] = 1;   // self loop
}

__global__ void count_kernel(const int* __restrict__ ei) {
    int i = blockIdx.x * blockDim.x + threadIdx.x;
    if (i < EE) atomicAdd(&g_deg[ei[EE + i]], 1);
}

__global__ __launch_bounds__(1024) void block_scan_kernel() {
    __shared__ int wsum[32];
    int lane = threadIdx.x & 31, wid = threadIdx.x >> 5;
    int i = blockIdx.x * 1024 + threadIdx.x;
    int v = (i < NN) ? g_deg[i] : 0;
    int x = v;
    #pragma unroll
    for (int d = 1; d < 32; d <<= 1) {
        int y = __shfl_up_sync(0xffffffffu, x, d);
        if (lane >= d) x += y;
    }
    if (lane == 31) wsum[wid] = x;
    __syncthreads();
    if (wid == 0) {
        int s = wsum[lane];
        #pragma unroll
        for (int d = 1; d < 32; d <<= 1) {
            int y = __shfl_up_sync(0xffffffffu, s, d);
            if (lane >= d) s += y;
        }
        wsum[lane] = s;
    }
    __syncthreads();
    int pre = wid ? wsum[wid - 1] : 0;
    if (i < NN) g_off[i] = pre + x - v;      // block-local exclusive
    if (threadIdx.x == 1023) g_bsum[blockIdx.x] = pre + x;
}

// add block prefixes (computed in-block), init cursors, set sentinel
__global__ __launch_bounds__(1024) void add_offsets_kernel() {
    __shared__ int pre;
    int bid = blockIdx.x;
    if (threadIdx.x < 32) {
        int s = 0;
        for (int i = threadIdx.x; i < bid; i += 32) s += g_bsum[i];
        #pragma unroll
        for (int o = 16; o; o >>= 1) s += __shfl_xor_sync(0xffffffffu, s, o);
        if (threadIdx.x == 0) pre = s;
    }
    __syncthreads();
    int i = bid * 1024 + threadIdx.x;
    if (i < NN) {
        int o = g_off[i] + pre;
        g_off[i] = o;
        g_cur[i] = o;
    }
    if (i == 0) g_off[NN] = ET;
}

__global__ void scatter_kernel(const int* __restrict__ ei) {
    int i = blockIdx.x * blockDim.x + threadIdx.x;
    if (i < ET) {
        int s, d;
        if (i < EE) { s = ei[i]; d = ei[EE + i]; }
        else        { s = i - EE; d = s; }
        int p = atomicAdd(&g_cur[d], 1);
        g_src[p] = s;
    }
}

// ---------------- tf32 tensor-core dual projection ----------------
// D(l,r)[128 x 64] += A[128 x K] * W(l,r)^T,  mma.m16n8k8 tf32
// block = 256 thr (8 warps); warp w owns rows 16w..16w+15, all 64 cols, both outputs.
__device__ __forceinline__ unsigned f2tf(float v) {
    unsigned u;
    asm("cvt.rna.tf32.f32 %0, %1;" : "=r"(u) : "f"(v));
    return u;
}

__global__ __launch_bounds__(256) void dual_linear_tc(
    const float* __restrict__ A, int fin,
    const float* __restrict__ Wl, const float* __restrict__ bl,
    const float* __restrict__ Wr, const float* __restrict__ br)
{
    // fragment-major smem: conflict-free LDS.128 (A) / LDS.64 (B)
    __shared__ unsigned Af[8 * 4 * 32 * 4];    // [w][s][lane][4]   16KB
    __shared__ unsigned Blf[8 * 4 * 32 * 2];   // [n][s][lane][2]    8KB
    __shared__ unsigned Brf[8 * 4 * 32 * 2];   //                    8KB

    const int t    = threadIdx.x;
    const int lane = t & 31;
    const int w    = t >> 5;
    const int n0   = blockIdx.x * 128;

    float accl[8][4], accr[8][4];
    #pragma unroll
    for (int n = 0; n < 8; n++)
        #pragma unroll
        for (int j = 0; j < 4; j++) { accl[n][j] = 0.f; accr[n][j] = 0.f; }

    const int arow0 = t >> 3;        // A loader: row (+32/iter)
    const int acol4 = t & 7;         // float4 index along k-chunk
    const int wh    = t & 63;        // W loader: output row (h)
    const int wq    = t >> 6;        // 0..3 -> k-octet

    for (int kc = 0; kc < fin; kc += 32) {
        // ---- stage A chunk into fragment layout ----
        #pragma unroll
        for (int r = 0; r < 4; r++) {
            int row = arow0 + r * 32;
            const float4 v = *(const float4*)(A + (size_t)(n0 + row) * fin + kc + acol4 * 4);
            float vv[4] = {v.x, v.y, v.z, v.w};
            int wi = row >> 4, rl = row & 15;
            #pragma unroll
            for (int cc = 0; cc < 4; cc++) {
                int c  = acol4 * 4 + cc;
                int s  = c >> 3, c4 = c & 7;
                int j  = ((c4 >= 4) ? 2 : 0) + ((rl >= 8) ? 1 : 0);
                int ln = (rl & 7) * 4 + (c4 & 3);
                Af[(((wi * 4 + s) * 32) + ln) * 4 + j] = f2tf(vv[cc]);
            }
        }
        // ---- stage W chunks into fragment layout ----
        #pragma unroll
        for (int part = 0; part < 2; part++) {
            int kb = wq * 8 + part * 4;
            const float4 v = *(const float4*)(Wl + (size_t)wh * fin + kc + kb);
            const float4 u = *(const float4*)(Wr + (size_t)wh * fin + kc + kb);
            float vl[4] = {v.x, v.y, v.z, v.w};
            float vr[4] = {u.x, u.y, u.z, u.w};
            int nt = wh >> 3;
            #pragma unroll
            for (int cc = 0; cc < 4; cc++) {
                int k  = kb + cc;
                int s  = k >> 3;
                int j  = ((k & 7) >= 4) ? 1 : 0;
                int ln = (wh & 7) * 4 + (k & 3);
                int idx = (((nt * 4 + s) * 32) + ln) * 2 + j;
                Blf[idx] = f2tf(vl[cc]);
                Brf[idx] = f2tf(vr[cc]);
            }
        }
        __syncthreads();

        // ---- mma over 4 k-steps x 8 n-tiles x {l,r} ----
        #pragma unroll
        for (int s = 0; s < 4; s++) {
            uint4 a = *(const uint4*)(Af + (((w * 4 + s) * 32) + lane) * 4);
            #pragma unroll
            for (int n = 0; n < 8; n++) {
                uint2 b = *(const uint2*)(Blf + (((n * 4 + s) * 32) + lane) * 2);
                asm volatile(
                    "mma.sync.aligned.m16n8k8.row.col.f32.tf32.tf32.f32 "
                    "{%0,%1,%2,%3}, {%4,%5,%6,%7}, {%8,%9}, {%0,%1,%2,%3};"
                    : "+f"(accl[n][0]), "+f"(accl[n][1]), "+f"(accl[n][2]), "+f"(accl[n][3])
                    : "r"(a.x), "r"(a.y), "r"(a.z), "r"(a.w), "r"(b.x), "r"(b.y));
                uint2 c = *(const uint2*)(Brf + (((n * 4 + s) * 32) + lane) * 2);
                asm volatile(
                    "mma.sync.aligned.m16n8k8.row.col.f32.tf32.tf32.f32 "
                    "{%0,%1,%2,%3}, {%4,%5,%6,%7}, {%8,%9}, {%0,%1,%2,%3};"
                    : "+f"(accr[n][0]), "+f"(accr[n][1]), "+f"(accr[n][2]), "+f"(accr[n][3])
                    : "r"(a.x), "r"(a.y), "r"(a.z), "r"(a.w), "r"(c.x), "r"(c.y));
            }
        }
        __syncthreads();
    }

    // ---- epilogue: D fragment -> g_xl/g_xr (+bias) ----
    int r0 = n0 + w * 16 + (lane >> 2);
    int cq = (lane & 3) * 2;
    #pragma unroll
    for (int n = 0; n < 8; n++) {
        int col = n * 8 + cq;
        float2 bl2 = *(const float2*)(bl + col);
        float2 br2 = *(const float2*)(br + col);
        float2 o;
        o.x = accl[n][0] + bl2.x; o.y = accl[n][1] + bl2.y;
        *(float2*)(g_xl + (size_t)r0 * HH + col) = o;
        o.x = accl[n][2] + bl2.x; o.y = accl[n][3] + bl2.y;
        *(float2*)(g_xl + (size_t)(r0 + 8) * HH + col) = o;
        o.x = accr[n][0] + br2.x; o.y = accr[n][1] + br2.y;
        *(float2*)(g_xr + (size_t)r0 * HH + col) = o;
        o.x = accr[n][2] + br2.x; o.y = accr[n][3] + br2.y;
        *(float2*)(g_xr + (size_t)(r0 + 8) * HH + col) = o;
    }
}

// ---------------- per-destination online-softmax, 4 edges per warp-iteration ----------------
__global__ __launch_bounds__(256) void gat_edge_kernel(
    const float* __restrict__ att, const float* __restrict__ b,
    float* __restrict__ hout)
{
    int warp = blockIdx.x * (blockDim.x >> 5) + (threadIdx.x >> 5);
    if (warp >= NN) return;
    int lane = threadIdx.x & 31;
    int node = warp;

    float att0 = __ldg(att + lane);
    float att1 = __ldg(att + 32 + lane);
    float xr0  = g_xr[(size_t)node * HH + lane];
    float xr1  = g_xr[(size_t)node * HH + 32 + lane];

    int s = g_off[node], e = g_off[node + 1];

    float m = -3.0e38f, d = 0.f, acc0 = 0.f, acc1 = 0.f;
    for (int i = s; i < e; i += 4) {
        float a0[4], a1[4], p[4];
        #pragma unroll
        for (int j = 0; j < 4; j++) {
            bool valid = (i + j) < e;
            int src = valid ? g_src[i + j] : node;
            a0[j] = __ldg(g_xl + (size_t)src * HH + lane);
            a1[j] = __ldg(g_xl + (size_t)src * HH + 32 + lane);
            float t0 = a0[j] + xr0; t0 = t0 > 0.f ? t0 : 0.2f * t0;
            float t1 = a1[j] + xr1; t1 = t1 > 0.f ? t1 : 0.2f * t1;
            p[j] = valid ? (t0 * att0 + t1 * att1) : -3.0e38f;
        }
        #pragma unroll
        for (int o = 16; o; o >>= 1) {
            #pragma unroll
            for (int j = 0; j < 4; j++)
                p[j] += __shfl_xor_sync(0xffffffffu, p[j], o);
        }
        float m4 = fmaxf(fmaxf(p[0], p[1]), fmaxf(p[2], p[3]));
        if (m4 > m) {
            float sc = __expf(m - m4);
            d *= sc; acc0 *= sc; acc1 *= sc; m = m4;
        }
        #pragma unroll
        for (int j = 0; j < 4; j++) {
            float w = __expf(p[j] - m);
            d += w; acc0 += w * a0[j]; acc1 += w * a1[j];
        }
    }
    float inv = __fdividef(1.f, d);
    float o0 = acc0 * inv + __ldg(b + lane);
    float o1 = acc1 * inv + __ldg(b + 32 + lane);
    hout[(size_t)node * HH + lane]      = o0 > 0.f ? o0 : 0.f;
    hout[(size_t)node * HH + 32 + lane] = o1 > 0.f ? o1 : 0.f;
}

// ---------------- readout ----------------
__global__ __launch_bounds__(256) void readout_kernel(
    const float* __restrict__ h, const float* __restrict__ Wro,
    const float* __restrict__ bro, float* __restrict__ out)
{
    __shared__ float Ws[OUTD * HH];
    for (int i = threadIdx.x; i < OUTD * HH; i += blockDim.x) Ws[i] = Wro[i];
    __syncthreads();

    int warp = blockIdx.x * (blockDim.x >> 5) + (threadIdx.x >> 5);
    if (warp >= NN) return;
    int lane = threadIdx.x & 31;

    float h0 = h[(size_t)warp * HH + lane];
    float h1 = h[(size_t)warp * HH + 32 + lane];
    #pragma unroll
    for (int o = 0; o < OUTD; o++) {
        float p = h0 * Ws[o * HH + lane] + h1 * Ws[o * HH + 32 + lane];
        #pragma unroll
        for (int w = 16; w; w >>= 1) p += __shfl_xor_sync(0xffffffffu, p, w);
        if (lane == 0) out[(size_t)warp * OUTD + o] = p + __ldg(bro + o);
    }
}

// ---------------- launch ----------------
extern "C" void kernel_launch(void* const* d_in, const int* in_sizes, int n_in,
                              void* d_out, int out_size)
{
    const float* x  = (const float*)d_in[0];
    const int*   ei = (const int*)d_in[1];
    const float* Wl0 = (const float*)d_in[3];
    const float* bl0 = (const float*)d_in[4];
    const float* Wr0 = (const float*)d_in[5];
    const float* br0 = (const float*)d_in[6];
    const float* at0 = (const float*)d_in[7];
    const float* b0  = (const float*)d_in[8];
    const float* Wl1 = (const float*)d_in[9];
    const float* bl1 = (const float*)d_in[10];
    const float* Wr1 = (const float*)d_in[11];
    const float* br1 = (const float*)d_in[12];
    const float* at1 = (const float*)d_in[13];
    const float* b1  = (const float*)d_in[14];
    const float* Wl2 = (const float*)d_in[15];
    const float* bl2 = (const float*)d_in[16];
    const float* Wr2 = (const float*)d_in[17];
    const float* br2 = (const float*)d_in[18];
    const float* at2 = (const float*)d_in[19];
    const float* b2  = (const float*)d_in[20];
    const float* Wro = (const float*)d_in[21];
    const float* bro = (const float*)d_in[22];
    float* out = (float*)d_out;

    float *h1p, *h2p;
    cudaGetSymbolAddress((void**)&h1p, g_h1);
    cudaGetSymbolAddress((void**)&h2p, g_h2);

    const int NB = (NN + 1023) / 1024;   // 79 scan blocks

    deg_init_kernel<<<(NN + 255) / 256, 256>>>();
    count_kernel<<<(EE + 255) / 256, 256>>>(ei);
    block_scan_kernel<<<NB, 1024>>>();
    add_offsets_kernel<<<NB, 1024>>>();
    scatter_kernel<<<(ET + 255) / 256, 256>>>(ei);

    const int GB = NN / 128;         // 625
    const int WB = NN / 8;           // 10000

    dual_linear_tc<<<GB, 256>>>(x, FIND, Wl0, bl0, Wr0, br0);
    gat_edge_kernel<<<WB, 256>>>(at0, b0, h1p);
    dual_linear_tc<<<GB, 256>>>(h1p, HH, Wl1, bl1, Wr1, br1);
    gat_edge_kernel<<<WB, 256>>>(at1, b1, h2p);
    dual_linear_tc<<<GB, 256>>>(h2p, HH, Wl2, bl2, Wr2, br2);
    gat_edge_kernel<<<WB, 256>>>(at2, b2, h1p);
    readout_kernel<<<WB, 256>>>(h1p, Wro, bro, out);
}

// round 6
// speedup vs baseline: 1.6823x; 1.3354x over previous
#include <cuda_runtime.h>

#define NN   80000
#define EE   1280000
#define ET   (EE + NN)
#define HH   64
#define FIND 128
#define OUTD 10

// ---------------- scratch ----------------
__device__ float g_xl[(size_t)NN * HH];
__device__ float g_xr[(size_t)NN * HH];
__device__ float g_h1[(size_t)NN * HH];
__device__ float g_h2[(size_t)NN * HH];
__device__ int   g_deg[NN];
__device__ int   g_off[NN + 1];
__device__ int   g_cur[NN];
__device__ int   g_src[ET];
__device__ int   g_bsum[128];

// ---------------- CSR build ----------------
__global__ void deg_init_kernel() {
    int i = blockIdx.x * blockDim.x + threadIdx.x;
    if (i < NN) g_deg[i] = 1;   // self loop
}

__global__ void count_kernel(const int* __restrict__ ei) {
    int i = blockIdx.x * blockDim.x + threadIdx.x;
    if (i < EE) atomicAdd(&g_deg[ei[EE + i]], 1);
}

__global__ __launch_bounds__(1024) void block_scan_kernel() {
    __shared__ int wsum[32];
    int lane = threadIdx.x & 31, wid = threadIdx.x >> 5;
    int i = blockIdx.x * 1024 + threadIdx.x;
    int v = (i < NN) ? g_deg[i] : 0;
    int x = v;
    #pragma unroll
    for (int d = 1; d < 32; d <<= 1) {
        int y = __shfl_up_sync(0xffffffffu, x, d);
        if (lane >= d) x += y;
    }
    if (lane == 31) wsum[wid] = x;
    __syncthreads();
    if (wid == 0) {
        int s = wsum[lane];
        #pragma unroll
        for (int d = 1; d < 32; d <<= 1) {
            int y = __shfl_up_sync(0xffffffffu, s, d);
            if (lane >= d) s += y;
        }
        wsum[lane] = s;
    }
    __syncthreads();
    int pre = wid ? wsum[wid - 1] : 0;
    if (i < NN) g_off[i] = pre + x - v;      // block-local exclusive
    if (threadIdx.x == 1023) g_bsum[blockIdx.x] = pre + x;
}

__global__ __launch_bounds__(1024) void add_offsets_kernel() {
    __shared__ int pre;
    int bid = blockIdx.x;
    if (threadIdx.x < 32) {
        int s = 0;
        for (int i = threadIdx.x; i < bid; i += 32) s += g_bsum[i];
        #pragma unroll
        for (int o = 16; o; o >>= 1) s += __shfl_xor_sync(0xffffffffu, s, o);
        if (threadIdx.x == 0) pre = s;
    }
    __syncthreads();
    int i = bid * 1024 + threadIdx.x;
    if (i < NN) {
        int o = g_off[i] + pre;
        g_off[i] = o;
        g_cur[i] = o;
    }
    if (i == 0) g_off[NN] = ET;
}

__global__ void scatter_kernel(const int* __restrict__ ei) {
    int i = blockIdx.x * blockDim.x + threadIdx.x;
    if (i < ET) {
        int s, d;
        if (i < EE) { s = ei[i]; d = ei[EE + i]; }
        else        { s = i - EE; d = s; }
        int p = atomicAdd(&g_cur[d], 1);
        g_src[p] = s;
    }
}

// ---------------- tf32 tensor-core dual projection ----------------
__device__ __forceinline__ unsigned f2tf(float v) {
    unsigned u;
    asm("cvt.rna.tf32.f32 %0, %1;" : "=r"(u) : "f"(v));
    return u;
}

__global__ __launch_bounds__(256) void dual_linear_tc(
    const float* __restrict__ A, int fin,
    const float* __restrict__ Wl, const float* __restrict__ bl,
    const float* __restrict__ Wr, const float* __restrict__ br)
{
    __shared__ unsigned Af[8 * 4 * 32 * 4];    // [w][s][lane][4]   16KB
    __shared__ unsigned Blf[8 * 4 * 32 * 2];   // [n][s][lane][2]    8KB
    __shared__ unsigned Brf[8 * 4 * 32 * 2];   //                    8KB

    const int t    = threadIdx.x;
    const int lane = t & 31;
    const int w    = t >> 5;
    const int n0   = blockIdx.x * 128;

    float accl[8][4], accr[8][4];
    #pragma unroll
    for (int n = 0; n < 8; n++)
        #pragma unroll
        for (int j = 0; j < 4; j++) { accl[n][j] = 0.f; accr[n][j] = 0.f; }

    const int arow0 = t >> 3;
    const int acol4 = t & 7;
    const int wh    = t & 63;
    const int wq    = t >> 6;

    for (int kc = 0; kc < fin; kc += 32) {
        #pragma unroll
        for (int r = 0; r < 4; r++) {
            int row = arow0 + r * 32;
            const float4 v = *(const float4*)(A + (size_t)(n0 + row) * fin + kc + acol4 * 4);
            float vv[4] = {v.x, v.y, v.z, v.w};
            int wi = row >> 4, rl = row & 15;
            #pragma unroll
            for (int cc = 0; cc < 4; cc++) {
                int c  = acol4 * 4 + cc;
                int s  = c >> 3, c4 = c & 7;
                int j  = ((c4 >= 4) ? 2 : 0) + ((rl >= 8) ? 1 : 0);
                int ln = (rl & 7) * 4 + (c4 & 3);
                Af[(((wi * 4 + s) * 32) + ln) * 4 + j] = f2tf(vv[cc]);
            }
        }
        #pragma unroll
        for (int part = 0; part < 2; part++) {
            int kb = wq * 8 + part * 4;
            const float4 v = *(const float4*)(Wl + (size_t)wh * fin + kc + kb);
            const float4 u = *(const float4*)(Wr + (size_t)wh * fin + kc + kb);
            float vl[4] = {v.x, v.y, v.z, v.w};
            float vr[4] = {u.x, u.y, u.z, u.w};
            int nt = wh >> 3;
            #pragma unroll
            for (int cc = 0; cc < 4; cc++) {
                int k  = kb + cc;
                int s  = k >> 3;
                int j  = ((k & 7) >= 4) ? 1 : 0;
                int ln = (wh & 7) * 4 + (k & 3);
                int idx = (((nt * 4 + s) * 32) + ln) * 2 + j;
                Blf[idx] = f2tf(vl[cc]);
                Brf[idx] = f2tf(vr[cc]);
            }
        }
        __syncthreads();

        #pragma unroll
        for (int s = 0; s < 4; s++) {
            uint4 a = *(const uint4*)(Af + (((w * 4 + s) * 32) + lane) * 4);
            #pragma unroll
            for (int n = 0; n < 8; n++) {
                uint2 b = *(const uint2*)(Blf + (((n * 4 + s) * 32) + lane) * 2);
                asm volatile(
                    "mma.sync.aligned.m16n8k8.row.col.f32.tf32.tf32.f32 "
                    "{%0,%1,%2,%3}, {%4,%5,%6,%7}, {%8,%9}, {%0,%1,%2,%3};"
                    : "+f"(accl[n][0]), "+f"(accl[n][1]), "+f"(accl[n][2]), "+f"(accl[n][3])
                    : "r"(a.x), "r"(a.y), "r"(a.z), "r"(a.w), "r"(b.x), "r"(b.y));
                uint2 c = *(const uint2*)(Brf + (((n * 4 + s) * 32) + lane) * 2);
                asm volatile(
                    "mma.sync.aligned.m16n8k8.row.col.f32.tf32.tf32.f32 "
                    "{%0,%1,%2,%3}, {%4,%5,%6,%7}, {%8,%9}, {%0,%1,%2,%3};"
                    : "+f"(accr[n][0]), "+f"(accr[n][1]), "+f"(accr[n][2]), "+f"(accr[n][3])
                    : "r"(a.x), "r"(a.y), "r"(a.z), "r"(a.w), "r"(c.x), "r"(c.y));
            }
        }
        __syncthreads();
    }

    int r0 = n0 + w * 16 + (lane >> 2);
    int cq = (lane & 3) * 2;
    #pragma unroll
    for (int n = 0; n < 8; n++) {
        int col = n * 8 + cq;
        float2 bl2 = *(const float2*)(bl + col);
        float2 br2 = *(const float2*)(br + col);
        float2 o;
        o.x = accl[n][0] + bl2.x; o.y = accl[n][1] + bl2.y;
        *(float2*)(g_xl + (size_t)r0 * HH + col) = o;
        o.x = accl[n][2] + bl2.x; o.y = accl[n][3] + bl2.y;
        *(float2*)(g_xl + (size_t)(r0 + 8) * HH + col) = o;
        o.x = accr[n][0] + br2.x; o.y = accr[n][1] + br2.y;
        *(float2*)(g_xr + (size_t)r0 * HH + col) = o;
        o.x = accr[n][2] + br2.x; o.y = accr[n][3] + br2.y;
        *(float2*)(g_xr + (size_t)(r0 + 8) * HH + col) = o;
    }
}

// ---------------- half-warp-per-node online-softmax edge pass ----------------
// 16 lanes per node, 4 dims per lane (one LDG.128 per edge per lane).
// FINAL=true additionally applies the readout GEMV and writes [N,10].
template <bool FINAL>
__global__ __launch_bounds__(256) void gat_edge_half(
    const float* __restrict__ att, const float* __restrict__ b,
    float* __restrict__ hout,
    const float* __restrict__ Wro, const float* __restrict__ bro,
    float* __restrict__ out)
{
    __shared__ float Ws[OUTD * HH];
    if (FINAL) {
        for (int i = threadIdx.x; i < OUTD * HH; i += blockDim.x) Ws[i] = Wro[i];
        __syncthreads();
    }

    int lane = threadIdx.x & 31;
    int half = lane >> 4;
    int sl   = lane & 15;
    unsigned hm = 0xFFFFu << (half * 16);

    int node = (blockIdx.x * (blockDim.x >> 5) + (threadIdx.x >> 5)) * 2 + half;
    if (node >= NN) return;

    const float4 att4 = *(const float4*)(att + 4 * sl);
    const float4 xr4  = *(const float4*)(g_xr + (size_t)node * HH + 4 * sl);

    int s = g_off[node], e = g_off[node + 1];

    float m = -3.0e38f, d = 0.f;
    float4 acc = make_float4(0.f, 0.f, 0.f, 0.f);

    for (int i = s; i < e; i += 4) {
        float4 a[4];
        float  p[4];
        #pragma unroll
        for (int j = 0; j < 4; j++) {
            int src = (i + j < e) ? __ldg(g_src + i + j) : node;
            a[j] = *(const float4*)(g_xl + (size_t)src * HH + 4 * sl);
        }
        #pragma unroll
        for (int j = 0; j < 4; j++) {
            float t0 = a[j].x + xr4.x; t0 = t0 > 0.f ? t0 : 0.2f * t0;
            float t1 = a[j].y + xr4.y; t1 = t1 > 0.f ? t1 : 0.2f * t1;
            float t2 = a[j].z + xr4.z; t2 = t2 > 0.f ? t2 : 0.2f * t2;
            float t3 = a[j].w + xr4.w; t3 = t3 > 0.f ? t3 : 0.2f * t3;
            float q = t0 * att4.x + t1 * att4.y + t2 * att4.z + t3 * att4.w;
            p[j] = (i + j < e) ? q : -3.0e38f;
        }
        // 4 independent width-16 butterfly chains
        #pragma unroll
        for (int o = 8; o; o >>= 1) {
            #pragma unroll
            for (int j = 0; j < 4; j++)
                p[j] += __shfl_xor_sync(hm, p[j], o, 16);
        }
        float m4 = fmaxf(fmaxf(p[0], p[1]), fmaxf(p[2], p[3]));
        if (m4 > m) {                        // uniform within the half
            float sc = __expf(m - m4);
            d *= sc; acc.x *= sc; acc.y *= sc; acc.z *= sc; acc.w *= sc;
            m = m4;
        }
        #pragma unroll
        for (int j = 0; j < 4; j++) {
            float w = __expf(p[j] - m);      // padded lanes -> 0
            d += w;
            acc.x += w * a[j].x; acc.y += w * a[j].y;
            acc.z += w * a[j].z; acc.w += w * a[j].w;
        }
    }

    float inv = __fdividef(1.f, d);
    const float4 b4 = *(const float4*)(b + 4 * sl);
    float4 o4;
    o4.x = fmaxf(acc.x * inv + b4.x, 0.f);
    o4.y = fmaxf(acc.y * inv + b4.y, 0.f);
    o4.z = fmaxf(acc.z * inv + b4.z, 0.f);
    o4.w = fmaxf(acc.w * inv + b4.w, 0.f);

    if (!FINAL) {
        *(float4*)(hout + (size_t)node * HH + 4 * sl) = o4;
    } else {
        #pragma unroll
        for (int o = 0; o < OUTD; o++) {
            const float4 w4 = *(const float4*)(Ws + o * HH + 4 * sl);
            float q = o4.x * w4.x + o4.y * w4.y + o4.z * w4.z + o4.w * w4.w;
            #pragma unroll
            for (int r = 8; r; r >>= 1) q += __shfl_xor_sync(hm, q, r, 16);
            if (sl == 0) out[(size_t)node * OUTD + o] = q + __ldg(bro + o);
        }
    }
}

// ---------------- launch ----------------
extern "C" void kernel_launch(void* const* d_in, const int* in_sizes, int n_in,
                              void* d_out, int out_size)
{
    const float* x  = (const float*)d_in[0];
    const int*   ei = (const int*)d_in[1];
    const float* Wl0 = (const float*)d_in[3];
    const float* bl0 = (const float*)d_in[4];
    const float* Wr0 = (const float*)d_in[5];
    const float* br0 = (const float*)d_in[6];
    const float* at0 = (const float*)d_in[7];
    const float* b0  = (const float*)d_in[8];
    const float* Wl1 = (const float*)d_in[9];
    const float* bl1 = (const float*)d_in[10];
    const float* Wr1 = (const float*)d_in[11];
    const float* br1 = (const float*)d_in[12];
    const float* at1 = (const float*)d_in[13];
    const float* b1  = (const float*)d_in[14];
    const float* Wl2 = (const float*)d_in[15];
    const float* bl2 = (const float*)d_in[16];
    const float* Wr2 = (const float*)d_in[17];
    const float* br2 = (const float*)d_in[18];
    const float* at2 = (const float*)d_in[19];
    const float* b2  = (const float*)d_in[20];
    const float* Wro = (const float*)d_in[21];
    const float* bro = (const float*)d_in[22];
    float* out = (float*)d_out;

    float *h1p, *h2p;
    cudaGetSymbolAddress((void**)&h1p, g_h1);
    cudaGetSymbolAddress((void**)&h2p, g_h2);

    const int NB = (NN + 1023) / 1024;   // 79 scan blocks

    deg_init_kernel<<<(NN + 255) / 256, 256>>>();
    count_kernel<<<(EE + 255) / 256, 256>>>(ei);
    block_scan_kernel<<<NB, 1024>>>();
    add_offsets_kernel<<<NB, 1024>>>();
    scatter_kernel<<<(ET + 255) / 256, 256>>>(ei);

    const int GB = NN / 128;             // 625 GEMM blocks
    const int EB = NN / 16;              // 5000 edge blocks (16 nodes each)

    dual_linear_tc<<<GB, 256>>>(x, FIND, Wl0, bl0, Wr0, br0);
    gat_edge_half<false><<<EB, 256>>>(at0, b0, h1p, nullptr, nullptr, nullptr);
    dual_linear_tc<<<GB, 256>>>(h1p, HH, Wl1, bl1, Wr1, br1);
    gat_edge_half<false><<<EB, 256>>>(at1, b1, h2p, nullptr, nullptr, nullptr);
    dual_linear_tc<<<GB, 256>>>(h2p, HH, Wl2, bl2, Wr2, br2);
    gat_edge_half<true><<<EB, 256>>>(at2, b2, nullptr, Wro, bro, out);
}